// round 9
// baseline (speedup 1.0000x reference)
#include <cuda_runtime.h>
#include <cuda_fp16.h>
#include <cstdint>

// Luong dot attention via mma.sync.m16n8k16.f16.f32 (legacy HMMA path),
// 3-term error-compensated FP16 split (hh + hl + lh).
// R8: operands pre-split to fp16 hi/lo in gmem; GEMM mainloop is a pure
// cp.async 3-stage pipeline (no register staging / split ALU / STS bubble).
//   B=8, T=2048, S=2048, D=1024
// Output layout: [ctx (B*T*D) | weights (B*T*S)]; scores built in place.

#define B_ 8
#define T_ 2048
#define S_ 2048
#define D_ 1024

#define NQK ((size_t)B_ * T_ * D_)     // == B*S*D
#define NW  ((size_t)B_ * T_ * S_)

__device__ __align__(128) __half g_qh[NQK];
__device__ __align__(128) __half g_ql[NQK];
__device__ __align__(128) __half g_kh[NQK];
__device__ __align__(128) __half g_kl[NQK];
__device__ __align__(128) __half g_vh[NQK];   // V^T (B,D,S)
__device__ __align__(128) __half g_vl[NQK];
__device__ __align__(128) __half g_wh[NW];
__device__ __align__(128) __half g_wl[NW];

// ---------------------------------------------------------------- PTX helpers

__device__ __forceinline__ uint32_t smem_u32(const void* p) {
    uint32_t a;
    asm("{ .reg .u64 t; cvta.to.shared.u64 t, %1; cvt.u32.u64 %0, t; }"
        : "=r"(a) : "l"(p));
    return a;
}

__device__ __forceinline__ void cp16(uint32_t s, const void* g) {
    asm volatile("cp.async.cg.shared.global [%0], [%1], 16;"
                 :: "r"(s), "l"(__cvta_generic_to_global(g)) : "memory");
}
#define CP_COMMIT()  asm volatile("cp.async.commit_group;" ::: "memory")
#define CP_WAIT(n)   asm volatile("cp.async.wait_group %0;" :: "n"(n) : "memory")

#define LDSM4(r0, r1, r2, r3, addr)                                            \
    asm volatile("ldmatrix.sync.aligned.m8n8.x4.shared.b16 {%0,%1,%2,%3}, [%4];" \
                 : "=r"(r0), "=r"(r1), "=r"(r2), "=r"(r3) : "r"(addr))

#define MMA_F16(c, a, b)                                                       \
    asm volatile("mma.sync.aligned.m16n8k16.row.col.f32.f16.f16.f32 "          \
                 "{%0,%1,%2,%3}, {%4,%5,%6,%7}, {%8,%9}, {%0,%1,%2,%3};"       \
                 : "+f"((c)[0]), "+f"((c)[1]), "+f"((c)[2]), "+f"((c)[3])      \
                 : "r"((a)[0]), "r"((a)[1]), "r"((a)[2]), "r"((a)[3]),         \
                   "r"((b)[0]), "r"((b)[1]))

// Split a float4 into fp16 hi (rn) and fp16 lo (residual), packed as 2x half2.
__device__ __forceinline__ void split4(float4 v, uint2& hi, uint2& lo) {
    __half2 h0 = __floats2half2_rn(v.x, v.y);
    __half2 h1 = __floats2half2_rn(v.z, v.w);
    float2 f0 = __half22float2(h0);
    float2 f1 = __half22float2(h1);
    __half2 l0 = __floats2half2_rn(v.x - f0.x, v.y - f0.y);
    __half2 l1 = __floats2half2_rn(v.z - f1.x, v.w - f1.y);
    hi.x = *reinterpret_cast<uint32_t*>(&h0);
    hi.y = *reinterpret_cast<uint32_t*>(&h1);
    lo.x = *reinterpret_cast<uint32_t*>(&l0);
    lo.y = *reinterpret_cast<uint32_t*>(&l1);
}

// ---------------------------------------------------------------- GEMM kernel
// C[M,N] = (Ah+Al)[M,K] * (Bh+Bl)[N,K]^T  (fp16 k-major inputs, 3 MMA terms).
// CTA tile 128x128, K-chunk 64, 256 threads (8 warps, warp tile 64x32).
// 3 smem stages x { AHI 16K | ALO 16K | BHI 16K | BLO 16K } = 192 KB.

#define OFF_AHI 0
#define OFF_ALO 16384
#define OFF_BHI 32768
#define OFF_BLO 49152
#define STAGE_BYTES 65536
#define NSTAGE 3
#define SMEM_TOTAL (NSTAGE * STAGE_BYTES)

__global__ __launch_bounds__(256, 1) void gemm_f16pipe(
    const __half* __restrict__ Ah, const __half* __restrict__ Al,
    const __half* __restrict__ Bh, const __half* __restrict__ Bl,
    float* __restrict__ Cg, int lda, int ldb, int ldc, int K,
    size_t strideA, size_t strideB, size_t strideC)
{
    extern __shared__ char smem[];
    const uint32_t sb = smem_u32(smem);
    const int tid  = threadIdx.x;
    const int wid  = tid >> 5;
    const int lane = tid & 31;
    const size_t z = blockIdx.z;

    const __half* pAh = Ah + z * strideA + (size_t)(blockIdx.y * 128) * lda;
    const __half* pAl = Al + z * strideA + (size_t)(blockIdx.y * 128) * lda;
    const __half* pBh = Bh + z * strideB + (size_t)(blockIdx.x * 128) * ldb;
    const __half* pBl = Bl + z * strideB + (size_t)(blockIdx.x * 128) * ldb;
    float*        C   = Cg + z * strideC + (size_t)(blockIdx.y * 128) * ldc
                      + blockIdx.x * 128;

    const int warp_m = (wid & 1) * 64;
    const int warp_n = (wid >> 1) * 32;

    // ldmatrix thread geometry
    const int tile = lane >> 3;
    const int l8   = lane & 7;
    const int a_row0 = warp_m + ((tile & 1) << 3) + l8;   // + mi*16
    const int a_usel = tile >> 1;
    const int b_row0 = warp_n + ((tile >> 1) << 3) + l8;  // + nj*16
    const int b_usel = tile & 1;

    // Per-thread cp.async geometry: 4 x 16B per operand array per stage.
    const int cp_row = tid >> 1;          // base row pattern below
    (void)cp_row;

// Issue one stage's cp.asyncs (4 per array per thread) + commit.
#define CP_STAGE(SBASE, K0)                                                    \
    {                                                                          \
        _Pragma("unroll")                                                      \
        for (int j = 0; j < 4; j++) {                                          \
            int idx = tid + 256 * j;                                           \
            int row = idx >> 3, seg = idx & 7;                                 \
            uint32_t off = ((uint32_t)row << 7) | ((uint32_t)seg << 4);        \
            off ^= ((uint32_t)(row & 7) << 4);                                 \
            size_t ga = (size_t)row * lda + (K0) + seg * 8;                    \
            size_t gb = (size_t)row * ldb + (K0) + seg * 8;                    \
            cp16((SBASE) + OFF_AHI + off, pAh + ga);                           \
            cp16((SBASE) + OFF_ALO + off, pAl + ga);                           \
            cp16((SBASE) + OFF_BHI + off, pBh + gb);                           \
            cp16((SBASE) + OFF_BLO + off, pBl + gb);                           \
        }                                                                      \
        CP_COMMIT();                                                           \
    }

    const int nc = K / 64;

    // Prologue: stages 0 and 1 in flight.
    CP_STAGE(sb, 0)
    CP_STAGE(sb + STAGE_BYTES, 64)

    float acc[4][4][4];
#pragma unroll
    for (int i = 0; i < 4; i++)
#pragma unroll
        for (int j = 0; j < 4; j++) {
            acc[i][j][0] = 0.f; acc[i][j][1] = 0.f;
            acc[i][j][2] = 0.f; acc[i][j][3] = 0.f;
        }

    int cs = 0;  // stage holding chunk i

    for (int i = 0; i < nc; i++) {
        if (i + 1 < nc) { CP_WAIT(1); } else { CP_WAIT(0); }
        __syncthreads();

        if (i + 2 < nc) {
            int is = cs + 2; if (is >= NSTAGE) is -= NSTAGE;
            CP_STAGE(sb + (uint32_t)is * STAGE_BYTES, (i + 2) * 64)
        }

        const uint32_t st = sb + (uint32_t)cs * STAGE_BYTES;

#pragma unroll
        for (int ks = 0; ks < 4; ks++) {
            uint32_t ah[4][4], al[4][4], bh[4][2], bl[4][2];
#pragma unroll
            for (int mi = 0; mi < 4; mi++) {
                int row = a_row0 + mi * 16;
                uint32_t off = ((uint32_t)row << 7)
                             | ((uint32_t)((ks * 2 + a_usel) << 4) ^ ((uint32_t)(row & 7) << 4));
                LDSM4(ah[mi][0], ah[mi][1], ah[mi][2], ah[mi][3], st + OFF_AHI + off);
                LDSM4(al[mi][0], al[mi][1], al[mi][2], al[mi][3], st + OFF_ALO + off);
            }
#pragma unroll
            for (int nj = 0; nj < 2; nj++) {
                int row = b_row0 + nj * 16;
                uint32_t off = ((uint32_t)row << 7)
                             | ((uint32_t)((ks * 2 + b_usel) << 4) ^ ((uint32_t)(row & 7) << 4));
                LDSM4(bh[nj * 2][0], bh[nj * 2][1], bh[nj * 2 + 1][0], bh[nj * 2 + 1][1],
                      st + OFF_BHI + off);
                LDSM4(bl[nj * 2][0], bl[nj * 2][1], bl[nj * 2 + 1][0], bl[nj * 2 + 1][1],
                      st + OFF_BLO + off);
            }
#pragma unroll
            for (int mi = 0; mi < 4; mi++)
#pragma unroll
                for (int ni = 0; ni < 4; ni++)
                    MMA_F16(acc[mi][ni], ah[mi], bh[ni]);
#pragma unroll
            for (int mi = 0; mi < 4; mi++)
#pragma unroll
                for (int ni = 0; ni < 4; ni++)
                    MMA_F16(acc[mi][ni], ah[mi], bl[ni]);
#pragma unroll
            for (int mi = 0; mi < 4; mi++)
#pragma unroll
                for (int ni = 0; ni < 4; ni++)
                    MMA_F16(acc[mi][ni], al[mi], bh[ni]);
        }

        __syncthreads();   // everyone done reading stage cs before it refills
        cs = cs + 1; if (cs >= NSTAGE) cs -= NSTAGE;
    }

    // Epilogue
    const int erow = warp_m + (lane >> 2);
    const int ecol = warp_n + 2 * (lane & 3);
#pragma unroll
    for (int mi = 0; mi < 4; mi++) {
#pragma unroll
        for (int ni = 0; ni < 4; ni++) {
            float* cp = C + (size_t)(erow + mi * 16) * ldc + ecol + ni * 8;
            *(float2*)cp = make_float2(acc[mi][ni][0], acc[mi][ni][1]);
            *(float2*)(cp + (size_t)8 * ldc) = make_float2(acc[mi][ni][2], acc[mi][ni][3]);
        }
    }
}

// ------------------------------------------------- split fp32 -> fp16 hi/lo

__global__ void split_f32(const float* __restrict__ in,
                          __half* __restrict__ hi, __half* __restrict__ lo,
                          int n4)
{
    int idx = blockIdx.x * blockDim.x + threadIdx.x;
    if (idx < n4) {
        float4 v = ((const float4*)in)[idx];
        uint2 h, l;
        split4(v, h, l);
        ((uint2*)hi)[idx] = h;
        ((uint2*)lo)[idx] = l;
    }
}

// ------------------------------------- transpose + split: vT hi/lo from src

__global__ void transpose_split(const float* __restrict__ src,
                                __half* __restrict__ vh, __half* __restrict__ vl)
{
    __shared__ float t[32][33];
    const int b = blockIdx.z;
    const int s0 = blockIdx.x * 32;
    const int d0 = blockIdx.y * 32;
    const float* sp = src + (size_t)b * S_ * D_;
    __half* hp = vh + (size_t)b * D_ * S_;
    __half* lp = vl + (size_t)b * D_ * S_;
    const int tx = threadIdx.x, ty = threadIdx.y;
#pragma unroll
    for (int i = 0; i < 32; i += 8)
        t[ty + i][tx] = sp[(size_t)(s0 + ty + i) * D_ + d0 + tx];
    __syncthreads();
#pragma unroll
    for (int i = 0; i < 32; i += 8) {
        float v = t[tx][ty + i];
        __half h = __float2half_rn(v);
        __half l = __float2half_rn(v - __half2float(h));
        size_t o = (size_t)(d0 + ty + i) * S_ + s0 + tx;
        hp[o] = h;
        lp[o] = l;
    }
}

// ---------------------------------------------------------------- softmax
// In-place softmax over S; also emits fp16 hi/lo of the weights.

__global__ void softmax_rows(float* __restrict__ w,
                             __half* __restrict__ wh, __half* __restrict__ wl)
{
    __shared__ float redm[8];
    __shared__ float reds[8];
    const int tid  = threadIdx.x;
    const int lane = tid & 31;
    const int wid  = tid >> 5;
    const size_t roff = (size_t)blockIdx.x * S_;
    float* p = w + roff;

    float4 v0 = *(const float4*)(p + tid * 4);
    float4 v1 = *(const float4*)(p + 1024 + tid * 4);

    float mx = fmaxf(fmaxf(fmaxf(v0.x, v0.y), fmaxf(v0.z, v0.w)),
                     fmaxf(fmaxf(v1.x, v1.y), fmaxf(v1.z, v1.w)));
#pragma unroll
    for (int o = 16; o; o >>= 1)
        mx = fmaxf(mx, __shfl_xor_sync(0xffffffffu, mx, o));
    if (lane == 0) redm[wid] = mx;
    __syncthreads();
    if (tid < 32) {
        float m = (tid < 8) ? redm[tid] : -3.402823466e38f;
#pragma unroll
        for (int o = 4; o; o >>= 1)
            m = fmaxf(m, __shfl_xor_sync(0xffffffffu, m, o));
        if (tid == 0) redm[0] = m;
    }
    __syncthreads();
    const float bm = redm[0];

    v0.x = __expf(v0.x - bm); v0.y = __expf(v0.y - bm);
    v0.z = __expf(v0.z - bm); v0.w = __expf(v0.w - bm);
    v1.x = __expf(v1.x - bm); v1.y = __expf(v1.y - bm);
    v1.z = __expf(v1.z - bm); v1.w = __expf(v1.w - bm);

    float sm = v0.x + v0.y + v0.z + v0.w + v1.x + v1.y + v1.z + v1.w;
#pragma unroll
    for (int o = 16; o; o >>= 1)
        sm += __shfl_xor_sync(0xffffffffu, sm, o);
    if (lane == 0) reds[wid] = sm;
    __syncthreads();
    if (tid < 32) {
        float t = (tid < 8) ? reds[tid] : 0.0f;
#pragma unroll
        for (int o = 4; o; o >>= 1)
            t += __shfl_xor_sync(0xffffffffu, t, o);
        if (tid == 0) reds[0] = t;
    }
    __syncthreads();
    const float inv = 1.0f / reds[0];

    v0.x *= inv; v0.y *= inv; v0.z *= inv; v0.w *= inv;
    v1.x *= inv; v1.y *= inv; v1.z *= inv; v1.w *= inv;
    *(float4*)(p + tid * 4)        = v0;
    *(float4*)(p + 1024 + tid * 4) = v1;

    uint2 h, l;
    split4(v0, h, l);
    *(uint2*)(wh + roff + tid * 4) = h;
    *(uint2*)(wl + roff + tid * 4) = l;
    split4(v1, h, l);
    *(uint2*)(wh + roff + 1024 + tid * 4) = h;
    *(uint2*)(wl + roff + 1024 + tid * 4) = l;
}

// ---------------------------------------------------------------- launch

extern "C" void kernel_launch(void* const* d_in, const int* in_sizes, int n_in,
                              void* d_out, int out_size)
{
    const float* trg = (const float*)d_in[0];   // (B, T, D)
    const float* src = (const float*)d_in[1];   // (B, S, D)
    float* ctx = (float*)d_out;                           // (B, T, D)
    float* wts = (float*)d_out + (size_t)B_ * T_ * D_;    // (B, T, S)

    __half *qh, *ql, *kh, *kl, *vh, *vl, *wh, *wl;
    void* p;
    cudaGetSymbolAddress(&p, g_qh); qh = (__half*)p;
    cudaGetSymbolAddress(&p, g_ql); ql = (__half*)p;
    cudaGetSymbolAddress(&p, g_kh); kh = (__half*)p;
    cudaGetSymbolAddress(&p, g_kl); kl = (__half*)p;
    cudaGetSymbolAddress(&p, g_vh); vh = (__half*)p;
    cudaGetSymbolAddress(&p, g_vl); vl = (__half*)p;
    cudaGetSymbolAddress(&p, g_wh); wh = (__half*)p;
    cudaGetSymbolAddress(&p, g_wl); wl = (__half*)p;

    cudaFuncSetAttribute(gemm_f16pipe,
                         cudaFuncAttributeMaxDynamicSharedMemorySize, SMEM_TOTAL);

    const int n4 = (int)(NQK / 4);

    // 1) split q, k ; transpose+split v
    split_f32<<<(n4 + 255) / 256, 256>>>(trg, qh, ql, n4);
    split_f32<<<(n4 + 255) / 256, 256>>>(src, kh, kl, n4);
    transpose_split<<<dim3(S_ / 32, D_ / 32, B_), dim3(32, 8)>>>(src, vh, vl);

    // 2) scores = q @ k^T
    gemm_f16pipe<<<dim3(S_ / 128, T_ / 128, B_), 256, SMEM_TOTAL>>>(
        qh, ql, kh, kl, wts, D_, D_, S_, D_,
        (size_t)T_ * D_, (size_t)S_ * D_, (size_t)T_ * S_);

    // 3) softmax rows in place + emit fp16 hi/lo weights
    softmax_rows<<<B_ * T_, 256>>>(wts, wh, wl);

    // 4) ctx = w @ vT^T
    gemm_f16pipe<<<dim3(D_ / 128, T_ / 128, B_), 256, SMEM_TOTAL>>>(
        wh, wl, vh, vl, ctx, S_, S_, D_, S_,
        (size_t)T_ * S_, (size_t)D_ * S_, (size_t)T_ * D_);
}

// round 11
// speedup vs baseline: 1.0269x; 1.0269x over previous
#include <cuda_runtime.h>
#include <cuda_fp16.h>
#include <cstdint>

// Luong dot attention via mma.sync.m16n8k16.f16.f32 (legacy HMMA path),
// 3-term error-compensated FP16 split (hh + hl + lh).
// R9: operands pre-split in gmem; GEMM = cp.async 2-stage pipeline,
// CTA tile 128x64, 96KB smem -> 2 CTAs/SM, ONE barrier per K-chunk.
//   B=8, T=2048, S=2048, D=1024
// Output layout: [ctx (B*T*D) | weights (B*T*S)]; scores built in place.

#define B_ 8
#define T_ 2048
#define S_ 2048
#define D_ 1024

#define NQK ((size_t)B_ * T_ * D_)     // == B*S*D
#define NW  ((size_t)B_ * T_ * S_)

__device__ __align__(128) __half g_qh[NQK];
__device__ __align__(128) __half g_ql[NQK];
__device__ __align__(128) __half g_kh[NQK];
__device__ __align__(128) __half g_kl[NQK];
__device__ __align__(128) __half g_vh[NQK];   // V^T (B,D,S)
__device__ __align__(128) __half g_vl[NQK];
__device__ __align__(128) __half g_wh[NW];
__device__ __align__(128) __half g_wl[NW];

// ---------------------------------------------------------------- PTX helpers

__device__ __forceinline__ uint32_t smem_u32(const void* p) {
    uint32_t a;
    asm("{ .reg .u64 t; cvta.to.shared.u64 t, %1; cvt.u32.u64 %0, t; }"
        : "=r"(a) : "l"(p));
    return a;
}

__device__ __forceinline__ void cp16(uint32_t s, const void* g) {
    asm volatile("cp.async.cg.shared.global [%0], [%1], 16;"
                 :: "r"(s), "l"(__cvta_generic_to_global(g)) : "memory");
}
#define CP_COMMIT()  asm volatile("cp.async.commit_group;" ::: "memory")
#define CP_WAIT(n)   asm volatile("cp.async.wait_group %0;" :: "n"(n) : "memory")

#define LDSM4(r0, r1, r2, r3, addr)                                            \
    asm volatile("ldmatrix.sync.aligned.m8n8.x4.shared.b16 {%0,%1,%2,%3}, [%4];" \
                 : "=r"(r0), "=r"(r1), "=r"(r2), "=r"(r3) : "r"(addr))

#define MMA_F16(c, a, b)                                                       \
    asm volatile("mma.sync.aligned.m16n8k16.row.col.f32.f16.f16.f32 "          \
                 "{%0,%1,%2,%3}, {%4,%5,%6,%7}, {%8,%9}, {%0,%1,%2,%3};"       \
                 : "+f"((c)[0]), "+f"((c)[1]), "+f"((c)[2]), "+f"((c)[3])      \
                 : "r"((a)[0]), "r"((a)[1]), "r"((a)[2]), "r"((a)[3]),         \
                   "r"((b)[0]), "r"((b)[1]))

// Split a float4 into fp16 hi (rn) and fp16 lo (residual), packed as 2x half2.
__device__ __forceinline__ void split4(float4 v, uint2& hi, uint2& lo) {
    __half2 h0 = __floats2half2_rn(v.x, v.y);
    __half2 h1 = __floats2half2_rn(v.z, v.w);
    float2 f0 = __half22float2(h0);
    float2 f1 = __half22float2(h1);
    __half2 l0 = __floats2half2_rn(v.x - f0.x, v.y - f0.y);
    __half2 l1 = __floats2half2_rn(v.z - f1.x, v.w - f1.y);
    hi.x = *reinterpret_cast<uint32_t*>(&h0);
    hi.y = *reinterpret_cast<uint32_t*>(&h1);
    lo.x = *reinterpret_cast<uint32_t*>(&l0);
    lo.y = *reinterpret_cast<uint32_t*>(&l1);
}

// ---------------------------------------------------------------- GEMM kernel
// C[M,N] = (Ah+Al)[M,K] * (Bh+Bl)[N,K]^T  (fp16 k-major, 3 MMA terms).
// CTA tile 128x64, K-chunk 64, 256 threads (8 warps, warp tile 32x32).
// 2 stages x { AHI 16K | ALO 16K | BHI 8K | BLO 8K } = 96 KB -> 2 CTAs/SM.

#define OFF_AHI 0
#define OFF_ALO 16384
#define OFF_BHI 32768
#define OFF_BLO 40960
#define STAGE_BYTES 49152
#define SMEM_TOTAL (2 * STAGE_BYTES)

__global__ __launch_bounds__(256, 2) void gemm_f16pipe(
    const __half* __restrict__ Ah, const __half* __restrict__ Al,
    const __half* __restrict__ Bh, const __half* __restrict__ Bl,
    float* __restrict__ Cg, int lda, int ldb, int ldc, int K,
    size_t strideA, size_t strideB, size_t strideC)
{
    extern __shared__ char smem[];
    const uint32_t sb = smem_u32(smem);
    const int tid  = threadIdx.x;
    const int wid  = tid >> 5;
    const int lane = tid & 31;
    const size_t z = blockIdx.z;

    const __half* pAh = Ah + z * strideA + (size_t)(blockIdx.y * 128) * lda;
    const __half* pAl = Al + z * strideA + (size_t)(blockIdx.y * 128) * lda;
    const __half* pBh = Bh + z * strideB + (size_t)(blockIdx.x * 64) * ldb;
    const __half* pBl = Bl + z * strideB + (size_t)(blockIdx.x * 64) * ldb;
    float*        C   = Cg + z * strideC + (size_t)(blockIdx.y * 128) * ldc
                      + blockIdx.x * 64;

    const int warp_m = (wid & 3) * 32;
    const int warp_n = (wid >> 2) * 32;

    // ldmatrix thread geometry
    const int tile = lane >> 3;
    const int l8   = lane & 7;
    const int a_row0 = warp_m + ((tile & 1) << 3) + l8;   // + mi*16
    const int a_usel = tile >> 1;
    const int b_row0 = warp_n + ((tile >> 1) << 3) + l8;  // + nj*16
    const int b_usel = tile & 1;

// Issue one stage's cp.asyncs (A: 4+4, B: 2+2 x16B per thread) + commit.
#define CP_STAGE(SBASE, K0)                                                    \
    {                                                                          \
        _Pragma("unroll")                                                      \
        for (int j = 0; j < 4; j++) {                                          \
            int idx = tid + 256 * j;                                           \
            int row = idx >> 3, seg = idx & 7;                                 \
            uint32_t off = ((uint32_t)row << 7) | ((uint32_t)seg << 4);        \
            off ^= ((uint32_t)(row & 7) << 4);                                 \
            size_t ga = (size_t)row * lda + (K0) + seg * 8;                    \
            cp16((SBASE) + OFF_AHI + off, pAh + ga);                           \
            cp16((SBASE) + OFF_ALO + off, pAl + ga);                           \
        }                                                                      \
        _Pragma("unroll")                                                      \
        for (int j = 0; j < 2; j++) {                                          \
            int idx = tid + 256 * j;                                           \
            int row = idx >> 3, seg = idx & 7;                                 \
            uint32_t off = ((uint32_t)row << 7) | ((uint32_t)seg << 4);        \
            off ^= ((uint32_t)(row & 7) << 4);                                 \
            size_t gb = (size_t)row * ldb + (K0) + seg * 8;                    \
            cp16((SBASE) + OFF_BHI + off, pBh + gb);                           \
            cp16((SBASE) + OFF_BLO + off, pBl + gb);                           \
        }                                                                      \
        CP_COMMIT();                                                           \
    }

    const int nc = K / 64;

    // Prologue: chunk 0 -> stage 0
    CP_STAGE(sb, 0)

    float acc[2][4][4];
#pragma unroll
    for (int i = 0; i < 2; i++)
#pragma unroll
        for (int j = 0; j < 4; j++) {
            acc[i][j][0] = 0.f; acc[i][j][1] = 0.f;
            acc[i][j][2] = 0.f; acc[i][j][3] = 0.f;
        }

    for (int i = 0; i < nc; i++) {
        CP_WAIT(0);
        __syncthreads();

        if (i + 1 < nc) {
            CP_STAGE(sb + (uint32_t)((i + 1) & 1) * STAGE_BYTES, (i + 1) * 64)
        }

        const uint32_t st = sb + (uint32_t)(i & 1) * STAGE_BYTES;

#pragma unroll
        for (int ks = 0; ks < 4; ks++) {
            uint32_t ah[2][4], al[2][4], bh[4][2], bl[4][2];
#pragma unroll
            for (int mi = 0; mi < 2; mi++) {
                int row = a_row0 + mi * 16;
                uint32_t off = ((uint32_t)row << 7)
                             | ((uint32_t)((ks * 2 + a_usel) << 4) ^ ((uint32_t)(row & 7) << 4));
                LDSM4(ah[mi][0], ah[mi][1], ah[mi][2], ah[mi][3], st + OFF_AHI + off);
                LDSM4(al[mi][0], al[mi][1], al[mi][2], al[mi][3], st + OFF_ALO + off);
            }
#pragma unroll
            for (int nj = 0; nj < 2; nj++) {
                int row = b_row0 + nj * 16;
                uint32_t off = ((uint32_t)row << 7)
                             | ((uint32_t)((ks * 2 + b_usel) << 4) ^ ((uint32_t)(row & 7) << 4));
                LDSM4(bh[nj * 2][0], bh[nj * 2][1], bh[nj * 2 + 1][0], bh[nj * 2 + 1][1],
                      st + OFF_BHI + off);
                LDSM4(bl[nj * 2][0], bl[nj * 2][1], bl[nj * 2 + 1][0], bl[nj * 2 + 1][1],
                      st + OFF_BLO + off);
            }
#pragma unroll
            for (int mi = 0; mi < 2; mi++)
#pragma unroll
                for (int ni = 0; ni < 4; ni++)
                    MMA_F16(acc[mi][ni], ah[mi], bh[ni]);
#pragma unroll
            for (int mi = 0; mi < 2; mi++)
#pragma unroll
                for (int ni = 0; ni < 4; ni++)
                    MMA_F16(acc[mi][ni], ah[mi], bl[ni]);
#pragma unroll
            for (int mi = 0; mi < 2; mi++)
#pragma unroll
                for (int ni = 0; ni < 4; ni++)
                    MMA_F16(acc[mi][ni], al[mi], bh[ni]);
        }
    }

    // Epilogue
    const int erow = warp_m + (lane >> 2);
    const int ecol = warp_n + 2 * (lane & 3);
#pragma unroll
    for (int mi = 0; mi < 2; mi++) {
#pragma unroll
        for (int ni = 0; ni < 4; ni++) {
            float* cp = C + (size_t)(erow + mi * 16) * ldc + ecol + ni * 8;
            *(float2*)cp = make_float2(acc[mi][ni][0], acc[mi][ni][1]);
            *(float2*)(cp + (size_t)8 * ldc) = make_float2(acc[mi][ni][2], acc[mi][ni][3]);
        }
    }
}

// ------------------------------------------------- split fp32 -> fp16 hi/lo

__global__ void split_f32(const float* __restrict__ in,
                          __half* __restrict__ hi, __half* __restrict__ lo,
                          int n4)
{
    int idx = blockIdx.x * blockDim.x + threadIdx.x;
    if (idx < n4) {
        float4 v = ((const float4*)in)[idx];
        uint2 h, l;
        split4(v, h, l);
        ((uint2*)hi)[idx] = h;
        ((uint2*)lo)[idx] = l;
    }
}

// ------------------------------------- transpose + split: vT hi/lo from src

__global__ void transpose_split(const float* __restrict__ src,
                                __half* __restrict__ vh, __half* __restrict__ vl)
{
    __shared__ float t[32][33];
    const int b = blockIdx.z;
    const int s0 = blockIdx.x * 32;
    const int d0 = blockIdx.y * 32;
    const float* sp = src + (size_t)b * S_ * D_;
    __half* hp = vh + (size_t)b * D_ * S_;
    __half* lp = vl + (size_t)b * D_ * S_;
    const int tx = threadIdx.x, ty = threadIdx.y;
#pragma unroll
    for (int i = 0; i < 32; i += 8)
        t[ty + i][tx] = sp[(size_t)(s0 + ty + i) * D_ + d0 + tx];
    __syncthreads();
#pragma unroll
    for (int i = 0; i < 32; i += 8) {
        float v = t[tx][ty + i];
        __half h = __float2half_rn(v);
        __half l = __float2half_rn(v - __half2float(h));
        size_t o = (size_t)(d0 + ty + i) * S_ + s0 + tx;
        hp[o] = h;
        lp[o] = l;
    }
}

// ---------------------------------------------------------------- softmax
// In-place softmax over S; also emits fp16 hi/lo of the weights.

__global__ void softmax_rows(float* __restrict__ w,
                             __half* __restrict__ wh, __half* __restrict__ wl)
{
    __shared__ float redm[8];
    __shared__ float reds[8];
    const int tid  = threadIdx.x;
    const int lane = tid & 31;
    const int wid  = tid >> 5;
    const size_t roff = (size_t)blockIdx.x * S_;
    float* p = w + roff;

    float4 v0 = *(const float4*)(p + tid * 4);
    float4 v1 = *(const float4*)(p + 1024 + tid * 4);

    float mx = fmaxf(fmaxf(fmaxf(v0.x, v0.y), fmaxf(v0.z, v0.w)),
                     fmaxf(fmaxf(v1.x, v1.y), fmaxf(v1.z, v1.w)));
#pragma unroll
    for (int o = 16; o; o >>= 1)
        mx = fmaxf(mx, __shfl_xor_sync(0xffffffffu, mx, o));
    if (lane == 0) redm[wid] = mx;
    __syncthreads();
    if (tid < 32) {
        float m = (tid < 8) ? redm[tid] : -3.402823466e38f;
#pragma unroll
        for (int o = 4; o; o >>= 1)
            m = fmaxf(m, __shfl_xor_sync(0xffffffffu, m, o));
        if (tid == 0) redm[0] = m;
    }
    __syncthreads();
    const float bm = redm[0];

    v0.x = __expf(v0.x - bm); v0.y = __expf(v0.y - bm);
    v0.z = __expf(v0.z - bm); v0.w = __expf(v0.w - bm);
    v1.x = __expf(v1.x - bm); v1.y = __expf(v1.y - bm);
    v1.z = __expf(v1.z - bm); v1.w = __expf(v1.w - bm);

    float sm = v0.x + v0.y + v0.z + v0.w + v1.x + v1.y + v1.z + v1.w;
#pragma unroll
    for (int o = 16; o; o >>= 1)
        sm += __shfl_xor_sync(0xffffffffu, sm, o);
    if (lane == 0) reds[wid] = sm;
    __syncthreads();
    if (tid < 32) {
        float t = (tid < 8) ? reds[tid] : 0.0f;
#pragma unroll
        for (int o = 4; o; o >>= 1)
            t += __shfl_xor_sync(0xffffffffu, t, o);
        if (tid == 0) reds[0] = t;
    }
    __syncthreads();
    const float inv = 1.0f / reds[0];

    v0.x *= inv; v0.y *= inv; v0.z *= inv; v0.w *= inv;
    v1.x *= inv; v1.y *= inv; v1.z *= inv; v1.w *= inv;
    *(float4*)(p + tid * 4)        = v0;
    *(float4*)(p + 1024 + tid * 4) = v1;

    uint2 h, l;
    split4(v0, h, l);
    *(uint2*)(wh + roff + tid * 4) = h;
    *(uint2*)(wl + roff + tid * 4) = l;
    split4(v1, h, l);
    *(uint2*)(wh + roff + 1024 + tid * 4) = h;
    *(uint2*)(wl + roff + 1024 + tid * 4) = l;
}

// ---------------------------------------------------------------- launch

extern "C" void kernel_launch(void* const* d_in, const int* in_sizes, int n_in,
                              void* d_out, int out_size)
{
    const float* trg = (const float*)d_in[0];   // (B, T, D)
    const float* src = (const float*)d_in[1];   // (B, S, D)
    float* ctx = (float*)d_out;                           // (B, T, D)
    float* wts = (float*)d_out + (size_t)B_ * T_ * D_;    // (B, T, S)

    __half *qh, *ql, *kh, *kl, *vh, *vl, *wh, *wl;
    void* p;
    cudaGetSymbolAddress(&p, g_qh); qh = (__half*)p;
    cudaGetSymbolAddress(&p, g_ql); ql = (__half*)p;
    cudaGetSymbolAddress(&p, g_kh); kh = (__half*)p;
    cudaGetSymbolAddress(&p, g_kl); kl = (__half*)p;
    cudaGetSymbolAddress(&p, g_vh); vh = (__half*)p;
    cudaGetSymbolAddress(&p, g_vl); vl = (__half*)p;
    cudaGetSymbolAddress(&p, g_wh); wh = (__half*)p;
    cudaGetSymbolAddress(&p, g_wl); wl = (__half*)p;

    cudaFuncSetAttribute(gemm_f16pipe,
                         cudaFuncAttributeMaxDynamicSharedMemorySize, SMEM_TOTAL);

    const int n4 = (int)(NQK / 4);

    // 1) split q, k ; transpose+split v
    split_f32<<<(n4 + 255) / 256, 256>>>(trg, qh, ql, n4);
    split_f32<<<(n4 + 255) / 256, 256>>>(src, kh, kl, n4);
    transpose_split<<<dim3(S_ / 32, D_ / 32, B_), dim3(32, 8)>>>(src, vh, vl);

    // 2) scores = q @ k^T
    gemm_f16pipe<<<dim3(S_ / 64, T_ / 128, B_), 256, SMEM_TOTAL>>>(
        qh, ql, kh, kl, wts, D_, D_, S_, D_,
        (size_t)T_ * D_, (size_t)S_ * D_, (size_t)T_ * S_);

    // 3) softmax rows in place + emit fp16 hi/lo weights
    softmax_rows<<<B_ * T_, 256>>>(wts, wh, wl);

    // 4) ctx = w @ vT^T
    gemm_f16pipe<<<dim3(D_ / 64, T_ / 128, B_), 256, SMEM_TOTAL>>>(
        wh, wl, vh, vl, ctx, S_, S_, D_, S_,
        (size_t)T_ * S_, (size_t)D_ * S_, (size_t)T_ * D_);
}

// round 12
// speedup vs baseline: 1.4769x; 1.4381x over previous
#include <cuda_runtime.h>
#include <cuda_fp16.h>
#include <cstdint>

// Luong dot attention via mma.sync.m16n8k16.f16.f32 (legacy HMMA path),
// 3-term error-compensated FP16 split (hh + hl + lh).
// R12: pre-split gmem operands; GEMM = CTA 128x128 (warp 64x32, 1:4 LDSM:MMA),
// K-chunk 32, cp.async 2-stage (32KB/stage -> 64KB/CTA -> 2 CTAs/SM),
// ONE barrier per chunk.
//   B=8, T=2048, S=2048, D=1024
// Output layout: [ctx (B*T*D) | weights (B*T*S)]; scores built in place.

#define B_ 8
#define T_ 2048
#define S_ 2048
#define D_ 1024

#define NQK ((size_t)B_ * T_ * D_)     // == B*S*D
#define NW  ((size_t)B_ * T_ * S_)

__device__ __align__(128) __half g_qh[NQK];
__device__ __align__(128) __half g_ql[NQK];
__device__ __align__(128) __half g_kh[NQK];
__device__ __align__(128) __half g_kl[NQK];
__device__ __align__(128) __half g_vh[NQK];   // V^T (B,D,S)
__device__ __align__(128) __half g_vl[NQK];
__device__ __align__(128) __half g_wh[NW];
__device__ __align__(128) __half g_wl[NW];

// ---------------------------------------------------------------- PTX helpers

__device__ __forceinline__ uint32_t smem_u32(const void* p) {
    uint32_t a;
    asm("{ .reg .u64 t; cvta.to.shared.u64 t, %1; cvt.u32.u64 %0, t; }"
        : "=r"(a) : "l"(p));
    return a;
}

__device__ __forceinline__ void cp16(uint32_t s, const void* g) {
    asm volatile("cp.async.cg.shared.global [%0], [%1], 16;"
                 :: "r"(s), "l"(__cvta_generic_to_global(g)) : "memory");
}
#define CP_COMMIT()  asm volatile("cp.async.commit_group;" ::: "memory")
#define CP_WAIT(n)   asm volatile("cp.async.wait_group %0;" :: "n"(n) : "memory")

#define LDSM4(r0, r1, r2, r3, addr)                                            \
    asm volatile("ldmatrix.sync.aligned.m8n8.x4.shared.b16 {%0,%1,%2,%3}, [%4];" \
                 : "=r"(r0), "=r"(r1), "=r"(r2), "=r"(r3) : "r"(addr))

#define MMA_F16(c, a, b)                                                       \
    asm volatile("mma.sync.aligned.m16n8k16.row.col.f32.f16.f16.f32 "          \
                 "{%0,%1,%2,%3}, {%4,%5,%6,%7}, {%8,%9}, {%0,%1,%2,%3};"       \
                 : "+f"((c)[0]), "+f"((c)[1]), "+f"((c)[2]), "+f"((c)[3])      \
                 : "r"((a)[0]), "r"((a)[1]), "r"((a)[2]), "r"((a)[3]),         \
                   "r"((b)[0]), "r"((b)[1]))

// Split a float4 into fp16 hi (rn) and fp16 lo (residual), packed as 2x half2.
__device__ __forceinline__ void split4(float4 v, uint2& hi, uint2& lo) {
    __half2 h0 = __floats2half2_rn(v.x, v.y);
    __half2 h1 = __floats2half2_rn(v.z, v.w);
    float2 f0 = __half22float2(h0);
    float2 f1 = __half22float2(h1);
    __half2 l0 = __floats2half2_rn(v.x - f0.x, v.y - f0.y);
    __half2 l1 = __floats2half2_rn(v.z - f1.x, v.w - f1.y);
    hi.x = *reinterpret_cast<uint32_t*>(&h0);
    hi.y = *reinterpret_cast<uint32_t*>(&h1);
    lo.x = *reinterpret_cast<uint32_t*>(&l0);
    lo.y = *reinterpret_cast<uint32_t*>(&l1);
}

// Swizzled offset within a 128-row x 32-half (64B/row) tile.
// 16B granule (row, c), c in 0..3:  off = row*64 + ((c ^ ((row>>1)&3))<<4)
// -> 8 consecutive rows at equal c hit 8 distinct 16B slots per 128B window.
__device__ __forceinline__ uint32_t swz(int row, int c) {
    return ((uint32_t)row << 6) | ((uint32_t)((c ^ ((row >> 1) & 3)) & 3) << 4);
}

// ---------------------------------------------------------------- GEMM kernel
// C[M,N] = (Ah+Al)[M,K] * (Bh+Bl)[N,K]^T  (fp16 k-major, 3 MMA terms).
// CTA tile 128x128, K-chunk 32, 256 threads (8 warps, warp tile 64x32).
// 2 stages x { AHI 8K | ALO 8K | BHI 8K | BLO 8K } = 64 KB -> 2 CTAs/SM.

#define OFF_AHI 0
#define OFF_ALO 8192
#define OFF_BHI 16384
#define OFF_BLO 24576
#define STAGE_BYTES 32768
#define SMEM_TOTAL (2 * STAGE_BYTES)

__global__ __launch_bounds__(256, 2) void gemm_f16pipe(
    const __half* __restrict__ Ah, const __half* __restrict__ Al,
    const __half* __restrict__ Bh, const __half* __restrict__ Bl,
    float* __restrict__ Cg, int lda, int ldb, int ldc, int K,
    size_t strideA, size_t strideB, size_t strideC)
{
    extern __shared__ char smem[];
    const uint32_t sb = smem_u32(smem);
    const int tid  = threadIdx.x;
    const int wid  = tid >> 5;
    const int lane = tid & 31;
    const size_t z = blockIdx.z;

    const __half* pAh = Ah + z * strideA + (size_t)(blockIdx.y * 128) * lda;
    const __half* pAl = Al + z * strideA + (size_t)(blockIdx.y * 128) * lda;
    const __half* pBh = Bh + z * strideB + (size_t)(blockIdx.x * 128) * ldb;
    const __half* pBl = Bl + z * strideB + (size_t)(blockIdx.x * 128) * ldb;
    float*        C   = Cg + z * strideC + (size_t)(blockIdx.y * 128) * ldc
                      + blockIdx.x * 128;

    const int warp_m = (wid & 1) * 64;
    const int warp_n = (wid >> 1) * 32;

    // ldmatrix thread geometry
    const int tile = lane >> 3;
    const int l8   = lane & 7;
    const int a_row0 = warp_m + ((tile & 1) << 3) + l8;   // + mi*16
    const int a_usel = tile >> 1;                         // 16B half of k16
    const int b_row0 = warp_n + ((tile >> 1) << 3) + l8;  // + nj*16
    const int b_usel = tile & 1;

// One stage: 2 x 16B per operand array per thread (8 cp16 total) + commit.
#define CP_STAGE(SBASE, K0)                                                    \
    {                                                                          \
        _Pragma("unroll")                                                      \
        for (int j = 0; j < 2; j++) {                                          \
            int idx = tid + 256 * j;                                           \
            int row = idx >> 2, c = idx & 3;                                   \
            uint32_t off = swz(row, c);                                        \
            size_t ga = (size_t)row * lda + (K0) + c * 8;                      \
            size_t gb = (size_t)row * ldb + (K0) + c * 8;                      \
            cp16((SBASE) + OFF_AHI + off, pAh + ga);                           \
            cp16((SBASE) + OFF_ALO + off, pAl + ga);                           \
            cp16((SBASE) + OFF_BHI + off, pBh + gb);                           \
            cp16((SBASE) + OFF_BLO + off, pBl + gb);                           \
        }                                                                      \
        CP_COMMIT();                                                           \
    }

    const int nc = K / 32;

    // Prologue: chunk 0 -> stage 0
    CP_STAGE(sb, 0)

    float acc[4][4][4];
#pragma unroll
    for (int i = 0; i < 4; i++)
#pragma unroll
        for (int j = 0; j < 4; j++) {
            acc[i][j][0] = 0.f; acc[i][j][1] = 0.f;
            acc[i][j][2] = 0.f; acc[i][j][3] = 0.f;
        }

    for (int i = 0; i < nc; i++) {
        CP_WAIT(0);
        __syncthreads();

        if (i + 1 < nc) {
            CP_STAGE(sb + (uint32_t)((i + 1) & 1) * STAGE_BYTES, (i + 1) * 32)
        }

        const uint32_t st = sb + (uint32_t)(i & 1) * STAGE_BYTES;

#pragma unroll
        for (int ks = 0; ks < 2; ks++) {
            uint32_t ah[4][4], al[4][4], bh[4][2], bl[4][2];
#pragma unroll
            for (int mi = 0; mi < 4; mi++) {
                int row = a_row0 + mi * 16;
                uint32_t off = swz(row, ks * 2 + a_usel);
                LDSM4(ah[mi][0], ah[mi][1], ah[mi][2], ah[mi][3], st + OFF_AHI + off);
                LDSM4(al[mi][0], al[mi][1], al[mi][2], al[mi][3], st + OFF_ALO + off);
            }
#pragma unroll
            for (int nj = 0; nj < 2; nj++) {
                int row = b_row0 + nj * 16;
                uint32_t off = swz(row, ks * 2 + b_usel);
                LDSM4(bh[nj * 2][0], bh[nj * 2][1], bh[nj * 2 + 1][0], bh[nj * 2 + 1][1],
                      st + OFF_BHI + off);
                LDSM4(bl[nj * 2][0], bl[nj * 2][1], bl[nj * 2 + 1][0], bl[nj * 2 + 1][1],
                      st + OFF_BLO + off);
            }
#pragma unroll
            for (int mi = 0; mi < 4; mi++)
#pragma unroll
                for (int ni = 0; ni < 4; ni++)
                    MMA_F16(acc[mi][ni], ah[mi], bh[ni]);
#pragma unroll
            for (int mi = 0; mi < 4; mi++)
#pragma unroll
                for (int ni = 0; ni < 4; ni++)
                    MMA_F16(acc[mi][ni], ah[mi], bl[ni]);
#pragma unroll
            for (int mi = 0; mi < 4; mi++)
#pragma unroll
                for (int ni = 0; ni < 4; ni++)
                    MMA_F16(acc[mi][ni], al[mi], bh[ni]);
        }
    }

    // Epilogue
    const int erow = warp_m + (lane >> 2);
    const int ecol = warp_n + 2 * (lane & 3);
#pragma unroll
    for (int mi = 0; mi < 4; mi++) {
#pragma unroll
        for (int ni = 0; ni < 4; ni++) {
            float* cp = C + (size_t)(erow + mi * 16) * ldc + ecol + ni * 8;
            *(float2*)cp = make_float2(acc[mi][ni][0], acc[mi][ni][1]);
            *(float2*)(cp + (size_t)8 * ldc) = make_float2(acc[mi][ni][2], acc[mi][ni][3]);
        }
    }
}

// ------------------------------------------------- split fp32 -> fp16 hi/lo

__global__ void split_f32(const float* __restrict__ in,
                          __half* __restrict__ hi, __half* __restrict__ lo,
                          int n4)
{
    int idx = blockIdx.x * blockDim.x + threadIdx.x;
    if (idx < n4) {
        float4 v = ((const float4*)in)[idx];
        uint2 h, l;
        split4(v, h, l);
        ((uint2*)hi)[idx] = h;
        ((uint2*)lo)[idx] = l;
    }
}

// ------------------------------------- transpose + split: vT hi/lo from src

__global__ void transpose_split(const float* __restrict__ src,
                                __half* __restrict__ vh, __half* __restrict__ vl)
{
    __shared__ float t[32][33];
    const int b = blockIdx.z;
    const int s0 = blockIdx.x * 32;
    const int d0 = blockIdx.y * 32;
    const float* sp = src + (size_t)b * S_ * D_;
    __half* hp = vh + (size_t)b * D_ * S_;
    __half* lp = vl + (size_t)b * D_ * S_;
    const int tx = threadIdx.x, ty = threadIdx.y;
#pragma unroll
    for (int i = 0; i < 32; i += 8)
        t[ty + i][tx] = sp[(size_t)(s0 + ty + i) * D_ + d0 + tx];
    __syncthreads();
#pragma unroll
    for (int i = 0; i < 32; i += 8) {
        float v = t[tx][ty + i];
        __half h = __float2half_rn(v);
        __half l = __float2half_rn(v - __half2float(h));
        size_t o = (size_t)(d0 + ty + i) * S_ + s0 + tx;
        hp[o] = h;
        lp[o] = l;
    }
}

// ---------------------------------------------------------------- softmax
// In-place softmax over S; also emits fp16 hi/lo of the weights.

__global__ void softmax_rows(float* __restrict__ w,
                             __half* __restrict__ wh, __half* __restrict__ wl)
{
    __shared__ float redm[8];
    __shared__ float reds[8];
    const int tid  = threadIdx.x;
    const int lane = tid & 31;
    const int wid  = tid >> 5;
    const size_t roff = (size_t)blockIdx.x * S_;
    float* p = w + roff;

    float4 v0 = *(const float4*)(p + tid * 4);
    float4 v1 = *(const float4*)(p + 1024 + tid * 4);

    float mx = fmaxf(fmaxf(fmaxf(v0.x, v0.y), fmaxf(v0.z, v0.w)),
                     fmaxf(fmaxf(v1.x, v1.y), fmaxf(v1.z, v1.w)));
#pragma unroll
    for (int o = 16; o; o >>= 1)
        mx = fmaxf(mx, __shfl_xor_sync(0xffffffffu, mx, o));
    if (lane == 0) redm[wid] = mx;
    __syncthreads();
    if (tid < 32) {
        float m = (tid < 8) ? redm[tid] : -3.402823466e38f;
#pragma unroll
        for (int o = 4; o; o >>= 1)
            m = fmaxf(m, __shfl_xor_sync(0xffffffffu, m, o));
        if (tid == 0) redm[0] = m;
    }
    __syncthreads();
    const float bm = redm[0];

    v0.x = __expf(v0.x - bm); v0.y = __expf(v0.y - bm);
    v0.z = __expf(v0.z - bm); v0.w = __expf(v0.w - bm);
    v1.x = __expf(v1.x - bm); v1.y = __expf(v1.y - bm);
    v1.z = __expf(v1.z - bm); v1.w = __expf(v1.w - bm);

    float sm = v0.x + v0.y + v0.z + v0.w + v1.x + v1.y + v1.z + v1.w;
#pragma unroll
    for (int o = 16; o; o >>= 1)
        sm += __shfl_xor_sync(0xffffffffu, sm, o);
    if (lane == 0) reds[wid] = sm;
    __syncthreads();
    if (tid < 32) {
        float t = (tid < 8) ? reds[tid] : 0.0f;
#pragma unroll
        for (int o = 4; o; o >>= 1)
            t += __shfl_xor_sync(0xffffffffu, t, o);
        if (tid == 0) reds[0] = t;
    }
    __syncthreads();
    const float inv = 1.0f / reds[0];

    v0.x *= inv; v0.y *= inv; v0.z *= inv; v0.w *= inv;
    v1.x *= inv; v1.y *= inv; v1.z *= inv; v1.w *= inv;
    *(float4*)(p + tid * 4)        = v0;
    *(float4*)(p + 1024 + tid * 4) = v1;

    uint2 h, l;
    split4(v0, h, l);
    *(uint2*)(wh + roff + tid * 4) = h;
    *(uint2*)(wl + roff + tid * 4) = l;
    split4(v1, h, l);
    *(uint2*)(wh + roff + 1024 + tid * 4) = h;
    *(uint2*)(wl + roff + 1024 + tid * 4) = l;
}

// ---------------------------------------------------------------- launch

extern "C" void kernel_launch(void* const* d_in, const int* in_sizes, int n_in,
                              void* d_out, int out_size)
{
    const float* trg = (const float*)d_in[0];   // (B, T, D)
    const float* src = (const float*)d_in[1];   // (B, S, D)
    float* ctx = (float*)d_out;                           // (B, T, D)
    float* wts = (float*)d_out + (size_t)B_ * T_ * D_;    // (B, T, S)

    __half *qh, *ql, *kh, *kl, *vh, *vl, *wh, *wl;
    void* p;
    cudaGetSymbolAddress(&p, g_qh); qh = (__half*)p;
    cudaGetSymbolAddress(&p, g_ql); ql = (__half*)p;
    cudaGetSymbolAddress(&p, g_kh); kh = (__half*)p;
    cudaGetSymbolAddress(&p, g_kl); kl = (__half*)p;
    cudaGetSymbolAddress(&p, g_vh); vh = (__half*)p;
    cudaGetSymbolAddress(&p, g_vl); vl = (__half*)p;
    cudaGetSymbolAddress(&p, g_wh); wh = (__half*)p;
    cudaGetSymbolAddress(&p, g_wl); wl = (__half*)p;

    cudaFuncSetAttribute(gemm_f16pipe,
                         cudaFuncAttributeMaxDynamicSharedMemorySize, SMEM_TOTAL);

    const int n4 = (int)(NQK / 4);

    // 1) split q, k ; transpose+split v
    split_f32<<<(n4 + 255) / 256, 256>>>(trg, qh, ql, n4);
    split_f32<<<(n4 + 255) / 256, 256>>>(src, kh, kl, n4);
    transpose_split<<<dim3(S_ / 32, D_ / 32, B_), dim3(32, 8)>>>(src, vh, vl);

    // 2) scores = q @ k^T
    gemm_f16pipe<<<dim3(S_ / 128, T_ / 128, B_), 256, SMEM_TOTAL>>>(
        qh, ql, kh, kl, wts, D_, D_, S_, D_,
        (size_t)T_ * D_, (size_t)S_ * D_, (size_t)T_ * S_);

    // 3) softmax rows in place + emit fp16 hi/lo weights
    softmax_rows<<<B_ * T_, 256>>>(wts, wh, wl);

    // 4) ctx = w @ vT^T
    gemm_f16pipe<<<dim3(D_ / 128, T_ / 128, B_), 256, SMEM_TOTAL>>>(
        wh, wl, vh, vl, ctx, S_, S_, D_, S_,
        (size_t)T_ * S_, (size_t)D_ * S_, (size_t)T_ * D_);
}

// round 13
// speedup vs baseline: 1.7611x; 1.1925x over previous
#include <cuda_runtime.h>
#include <cuda_fp16.h>
#include <cstdint>

// Luong dot attention via mma.sync.m16n8k16.f16.f32 (legacy HMMA path),
// error-compensated FP16 split.
// R13: 3-stage cp.async pipeline (CP_WAIT(1), 2-chunk latency cover),
// CTA 128x128 / warp 64x32, 2 CTAs/SM; GEMM1 = 3-term (hh+hl+lh),
// GEMM2 = 2-term (hh+hl; weights-lo term dropped, err ~1.6e-4 << 1e-3).
//   B=8, T=2048, S=2048, D=1024
// Output layout: [ctx (B*T*D) | weights (B*T*S)]; scores built in place.

#define B_ 8
#define T_ 2048
#define S_ 2048
#define D_ 1024

#define NQK ((size_t)B_ * T_ * D_)     // == B*S*D
#define NW  ((size_t)B_ * T_ * S_)

__device__ __align__(128) __half g_qh[NQK];
__device__ __align__(128) __half g_ql[NQK];
__device__ __align__(128) __half g_kh[NQK];
__device__ __align__(128) __half g_kl[NQK];
__device__ __align__(128) __half g_vh[NQK];   // V^T (B,D,S)
__device__ __align__(128) __half g_vl[NQK];
__device__ __align__(128) __half g_wh[NW];

// ---------------------------------------------------------------- PTX helpers

__device__ __forceinline__ uint32_t smem_u32(const void* p) {
    uint32_t a;
    asm("{ .reg .u64 t; cvta.to.shared.u64 t, %1; cvt.u32.u64 %0, t; }"
        : "=r"(a) : "l"(p));
    return a;
}

__device__ __forceinline__ void cp16(uint32_t s, const void* g) {
    asm volatile("cp.async.cg.shared.global [%0], [%1], 16;"
                 :: "r"(s), "l"(__cvta_generic_to_global(g)) : "memory");
}
#define CP_COMMIT()  asm volatile("cp.async.commit_group;" ::: "memory")
#define CP_WAIT(n)   asm volatile("cp.async.wait_group %0;" :: "n"(n) : "memory")

#define LDSM4(r0, r1, r2, r3, addr)                                            \
    asm volatile("ldmatrix.sync.aligned.m8n8.x4.shared.b16 {%0,%1,%2,%3}, [%4];" \
                 : "=r"(r0), "=r"(r1), "=r"(r2), "=r"(r3) : "r"(addr))

#define MMA_F16(c, a, b)                                                       \
    asm volatile("mma.sync.aligned.m16n8k16.row.col.f32.f16.f16.f32 "          \
                 "{%0,%1,%2,%3}, {%4,%5,%6,%7}, {%8,%9}, {%0,%1,%2,%3};"       \
                 : "+f"((c)[0]), "+f"((c)[1]), "+f"((c)[2]), "+f"((c)[3])      \
                 : "r"((a)[0]), "r"((a)[1]), "r"((a)[2]), "r"((a)[3]),         \
                   "r"((b)[0]), "r"((b)[1]))

// Split a float4 into fp16 hi (rn) and fp16 lo (residual), packed as 2x half2.
__device__ __forceinline__ void split4(float4 v, uint2& hi, uint2& lo) {
    __half2 h0 = __floats2half2_rn(v.x, v.y);
    __half2 h1 = __floats2half2_rn(v.z, v.w);
    float2 f0 = __half22float2(h0);
    float2 f1 = __half22float2(h1);
    __half2 l0 = __floats2half2_rn(v.x - f0.x, v.y - f0.y);
    __half2 l1 = __floats2half2_rn(v.z - f1.x, v.w - f1.y);
    hi.x = *reinterpret_cast<uint32_t*>(&h0);
    hi.y = *reinterpret_cast<uint32_t*>(&h1);
    lo.x = *reinterpret_cast<uint32_t*>(&l0);
    lo.y = *reinterpret_cast<uint32_t*>(&l1);
}

// Swizzled offset within a 128-row x 32-half (64B/row) tile.
__device__ __forceinline__ uint32_t swz(int row, int c) {
    return ((uint32_t)row << 6) | ((uint32_t)((c ^ ((row >> 1) & 3)) & 3) << 4);
}

// ---------------------------------------------------------------- GEMM kernel
// C[M,N] = (Ah[+Al]) [M,K] * (Bh+Bl)[N,K]^T   (fp16 k-major).
// TERMS=3: hh + hl + lh.  TERMS=2: hh + hl (Al unused, not loaded).
// CTA 128x128, K-chunk 32, 256 threads (8 warps, warp tile 64x32).
// 3 stages x { AHI 8K | ALO 8K | BHI 8K | BLO 8K } = 96 KB -> 2 CTAs/SM.

#define OFF_AHI 0
#define OFF_ALO 8192
#define OFF_BHI 16384
#define OFF_BLO 24576
#define STAGE_BYTES 32768
#define NSTAGE 3
#define SMEM_TOTAL (NSTAGE * STAGE_BYTES)

template <int TERMS>
__global__ __launch_bounds__(256, 2) void gemm_f16pipe(
    const __half* __restrict__ Ah, const __half* __restrict__ Al,
    const __half* __restrict__ Bh, const __half* __restrict__ Bl,
    float* __restrict__ Cg, int lda, int ldb, int ldc, int K,
    size_t strideA, size_t strideB, size_t strideC)
{
    extern __shared__ char smem[];
    const uint32_t sb = smem_u32(smem);
    const int tid  = threadIdx.x;
    const int wid  = tid >> 5;
    const int lane = tid & 31;
    const size_t z = blockIdx.z;

    const __half* pAh = Ah + z * strideA + (size_t)(blockIdx.y * 128) * lda;
    const __half* pAl = Al + z * strideA + (size_t)(blockIdx.y * 128) * lda;
    const __half* pBh = Bh + z * strideB + (size_t)(blockIdx.x * 128) * ldb;
    const __half* pBl = Bl + z * strideB + (size_t)(blockIdx.x * 128) * ldb;
    float*        C   = Cg + z * strideC + (size_t)(blockIdx.y * 128) * ldc
                      + blockIdx.x * 128;

    const int warp_m = (wid & 1) * 64;
    const int warp_n = (wid >> 1) * 32;

    // ldmatrix thread geometry
    const int tile = lane >> 3;
    const int l8   = lane & 7;
    const int a_row0 = warp_m + ((tile & 1) << 3) + l8;   // + mi*16
    const int a_usel = tile >> 1;                         // 16B half of k16
    const int b_row0 = warp_n + ((tile >> 1) << 3) + l8;  // + nj*16
    const int b_usel = tile & 1;

// One stage's cp.asyncs + commit.
#define CP_STAGE(SBASE, K0)                                                    \
    {                                                                          \
        _Pragma("unroll")                                                      \
        for (int j = 0; j < 2; j++) {                                          \
            int idx = tid + 256 * j;                                           \
            int row = idx >> 2, c = idx & 3;                                   \
            uint32_t off = swz(row, c);                                        \
            size_t ga = (size_t)row * lda + (K0) + c * 8;                      \
            size_t gb = (size_t)row * ldb + (K0) + c * 8;                      \
            cp16((SBASE) + OFF_AHI + off, pAh + ga);                           \
            if (TERMS == 3) cp16((SBASE) + OFF_ALO + off, pAl + ga);           \
            cp16((SBASE) + OFF_BHI + off, pBh + gb);                           \
            cp16((SBASE) + OFF_BLO + off, pBl + gb);                           \
        }                                                                      \
        CP_COMMIT();                                                           \
    }

    const int nc = K / 32;

    // Prologue: chunks 0,1 -> stages 0,1.
    CP_STAGE(sb, 0)
    CP_STAGE(sb + STAGE_BYTES, 32)

    float acc[4][4][4];
#pragma unroll
    for (int i = 0; i < 4; i++)
#pragma unroll
        for (int j = 0; j < 4; j++) {
            acc[i][j][0] = 0.f; acc[i][j][1] = 0.f;
            acc[i][j][2] = 0.f; acc[i][j][3] = 0.f;
        }

    int cs = 0;  // stage holding chunk i

    for (int i = 0; i < nc; i++) {
        if (i == nc - 1) { CP_WAIT(0); } else { CP_WAIT(1); }
        __syncthreads();

        if (i + 2 < nc) {
            int is = cs + 2; if (is >= NSTAGE) is -= NSTAGE;
            CP_STAGE(sb + (uint32_t)is * STAGE_BYTES, (i + 2) * 32)
        }

        const uint32_t st = sb + (uint32_t)cs * STAGE_BYTES;

#pragma unroll
        for (int ks = 0; ks < 2; ks++) {
            uint32_t ah[4][4], al[4][4], bh[4][2], bl[4][2];
#pragma unroll
            for (int mi = 0; mi < 4; mi++) {
                int row = a_row0 + mi * 16;
                uint32_t off = swz(row, ks * 2 + a_usel);
                LDSM4(ah[mi][0], ah[mi][1], ah[mi][2], ah[mi][3], st + OFF_AHI + off);
                if (TERMS == 3)
                    LDSM4(al[mi][0], al[mi][1], al[mi][2], al[mi][3], st + OFF_ALO + off);
            }
#pragma unroll
            for (int nj = 0; nj < 2; nj++) {
                int row = b_row0 + nj * 16;
                uint32_t off = swz(row, ks * 2 + b_usel);
                LDSM4(bh[nj * 2][0], bh[nj * 2][1], bh[nj * 2 + 1][0], bh[nj * 2 + 1][1],
                      st + OFF_BHI + off);
                LDSM4(bl[nj * 2][0], bl[nj * 2][1], bl[nj * 2 + 1][0], bl[nj * 2 + 1][1],
                      st + OFF_BLO + off);
            }
#pragma unroll
            for (int mi = 0; mi < 4; mi++)
#pragma unroll
                for (int ni = 0; ni < 4; ni++)
                    MMA_F16(acc[mi][ni], ah[mi], bh[ni]);
#pragma unroll
            for (int mi = 0; mi < 4; mi++)
#pragma unroll
                for (int ni = 0; ni < 4; ni++)
                    MMA_F16(acc[mi][ni], ah[mi], bl[ni]);
            if (TERMS == 3) {
#pragma unroll
                for (int mi = 0; mi < 4; mi++)
#pragma unroll
                    for (int ni = 0; ni < 4; ni++)
                        MMA_F16(acc[mi][ni], al[mi], bh[ni]);
            }
        }

        cs = cs + 1; if (cs >= NSTAGE) cs -= NSTAGE;
    }

    // Epilogue
    const int erow = warp_m + (lane >> 2);
    const int ecol = warp_n + 2 * (lane & 3);
#pragma unroll
    for (int mi = 0; mi < 4; mi++) {
#pragma unroll
        for (int ni = 0; ni < 4; ni++) {
            float* cp = C + (size_t)(erow + mi * 16) * ldc + ecol + ni * 8;
            *(float2*)cp = make_float2(acc[mi][ni][0], acc[mi][ni][1]);
            *(float2*)(cp + (size_t)8 * ldc) = make_float2(acc[mi][ni][2], acc[mi][ni][3]);
        }
    }
}

// ------------------------------------------------- split fp32 -> fp16 hi/lo

__global__ void split_f32(const float* __restrict__ in,
                          __half* __restrict__ hi, __half* __restrict__ lo,
                          int n4)
{
    int idx = blockIdx.x * blockDim.x + threadIdx.x;
    if (idx < n4) {
        float4 v = ((const float4*)in)[idx];
        uint2 h, l;
        split4(v, h, l);
        ((uint2*)hi)[idx] = h;
        ((uint2*)lo)[idx] = l;
    }
}

// ------------------------------------- transpose + split: vT hi/lo from src

__global__ void transpose_split(const float* __restrict__ src,
                                __half* __restrict__ vh, __half* __restrict__ vl)
{
    __shared__ float t[32][33];
    const int b = blockIdx.z;
    const int s0 = blockIdx.x * 32;
    const int d0 = blockIdx.y * 32;
    const float* sp = src + (size_t)b * S_ * D_;
    __half* hp = vh + (size_t)b * D_ * S_;
    __half* lp = vl + (size_t)b * D_ * S_;
    const int tx = threadIdx.x, ty = threadIdx.y;
#pragma unroll
    for (int i = 0; i < 32; i += 8)
        t[ty + i][tx] = sp[(size_t)(s0 + ty + i) * D_ + d0 + tx];
    __syncthreads();
#pragma unroll
    for (int i = 0; i < 32; i += 8) {
        float v = t[tx][ty + i];
        __half h = __float2half_rn(v);
        __half l = __float2half_rn(v - __half2float(h));
        size_t o = (size_t)(d0 + ty + i) * S_ + s0 + tx;
        hp[o] = h;
        lp[o] = l;
    }
}

// ---------------------------------------------------------------- softmax
// In-place softmax over S; also emits fp16 hi of the weights (GEMM2 2-term).

__global__ void softmax_rows(float* __restrict__ w, __half* __restrict__ wh)
{
    __shared__ float redm[8];
    __shared__ float reds[8];
    const int tid  = threadIdx.x;
    const int lane = tid & 31;
    const int wid  = tid >> 5;
    const size_t roff = (size_t)blockIdx.x * S_;
    float* p = w + roff;

    float4 v0 = *(const float4*)(p + tid * 4);
    float4 v1 = *(const float4*)(p + 1024 + tid * 4);

    float mx = fmaxf(fmaxf(fmaxf(v0.x, v0.y), fmaxf(v0.z, v0.w)),
                     fmaxf(fmaxf(v1.x, v1.y), fmaxf(v1.z, v1.w)));
#pragma unroll
    for (int o = 16; o; o >>= 1)
        mx = fmaxf(mx, __shfl_xor_sync(0xffffffffu, mx, o));
    if (lane == 0) redm[wid] = mx;
    __syncthreads();
    if (tid < 32) {
        float m = (tid < 8) ? redm[tid] : -3.402823466e38f;
#pragma unroll
        for (int o = 4; o; o >>= 1)
            m = fmaxf(m, __shfl_xor_sync(0xffffffffu, m, o));
        if (tid == 0) redm[0] = m;
    }
    __syncthreads();
    const float bm = redm[0];

    v0.x = __expf(v0.x - bm); v0.y = __expf(v0.y - bm);
    v0.z = __expf(v0.z - bm); v0.w = __expf(v0.w - bm);
    v1.x = __expf(v1.x - bm); v1.y = __expf(v1.y - bm);
    v1.z = __expf(v1.z - bm); v1.w = __expf(v1.w - bm);

    float sm = v0.x + v0.y + v0.z + v0.w + v1.x + v1.y + v1.z + v1.w;
#pragma unroll
    for (int o = 16; o; o >>= 1)
        sm += __shfl_xor_sync(0xffffffffu, sm, o);
    if (lane == 0) reds[wid] = sm;
    __syncthreads();
    if (tid < 32) {
        float t = (tid < 8) ? reds[tid] : 0.0f;
#pragma unroll
        for (int o = 4; o; o >>= 1)
            t += __shfl_xor_sync(0xffffffffu, t, o);
        if (tid == 0) reds[0] = t;
    }
    __syncthreads();
    const float inv = 1.0f / reds[0];

    v0.x *= inv; v0.y *= inv; v0.z *= inv; v0.w *= inv;
    v1.x *= inv; v1.y *= inv; v1.z *= inv; v1.w *= inv;
    *(float4*)(p + tid * 4)        = v0;
    *(float4*)(p + 1024 + tid * 4) = v1;

    __half2 h0 = __floats2half2_rn(v0.x, v0.y);
    __half2 h1 = __floats2half2_rn(v0.z, v0.w);
    __half2 h2 = __floats2half2_rn(v1.x, v1.y);
    __half2 h3 = __floats2half2_rn(v1.z, v1.w);
    uint2 u0, u1;
    u0.x = *reinterpret_cast<uint32_t*>(&h0);
    u0.y = *reinterpret_cast<uint32_t*>(&h1);
    u1.x = *reinterpret_cast<uint32_t*>(&h2);
    u1.y = *reinterpret_cast<uint32_t*>(&h3);
    *(uint2*)(wh + roff + tid * 4)        = u0;
    *(uint2*)(wh + roff + 1024 + tid * 4) = u1;
}

// ---------------------------------------------------------------- launch

extern "C" void kernel_launch(void* const* d_in, const int* in_sizes, int n_in,
                              void* d_out, int out_size)
{
    const float* trg = (const float*)d_in[0];   // (B, T, D)
    const float* src = (const float*)d_in[1];   // (B, S, D)
    float* ctx = (float*)d_out;                           // (B, T, D)
    float* wts = (float*)d_out + (size_t)B_ * T_ * D_;    // (B, T, S)

    __half *qh, *ql, *kh, *kl, *vh, *vl, *wh;
    void* p;
    cudaGetSymbolAddress(&p, g_qh); qh = (__half*)p;
    cudaGetSymbolAddress(&p, g_ql); ql = (__half*)p;
    cudaGetSymbolAddress(&p, g_kh); kh = (__half*)p;
    cudaGetSymbolAddress(&p, g_kl); kl = (__half*)p;
    cudaGetSymbolAddress(&p, g_vh); vh = (__half*)p;
    cudaGetSymbolAddress(&p, g_vl); vl = (__half*)p;
    cudaGetSymbolAddress(&p, g_wh); wh = (__half*)p;

    cudaFuncSetAttribute(gemm_f16pipe<3>,
                         cudaFuncAttributeMaxDynamicSharedMemorySize, SMEM_TOTAL);
    cudaFuncSetAttribute(gemm_f16pipe<2>,
                         cudaFuncAttributeMaxDynamicSharedMemorySize, SMEM_TOTAL);

    const int n4 = (int)(NQK / 4);

    // 1) split q, k ; transpose+split v
    split_f32<<<(n4 + 255) / 256, 256>>>(trg, qh, ql, n4);
    split_f32<<<(n4 + 255) / 256, 256>>>(src, kh, kl, n4);
    transpose_split<<<dim3(S_ / 32, D_ / 32, B_), dim3(32, 8)>>>(src, vh, vl);

    // 2) scores = q @ k^T  (3-term)
    gemm_f16pipe<3><<<dim3(S_ / 128, T_ / 128, B_), 256, SMEM_TOTAL>>>(
        qh, ql, kh, kl, wts, D_, D_, S_, D_,
        (size_t)T_ * D_, (size_t)S_ * D_, (size_t)T_ * S_);

    // 3) softmax rows in place + emit fp16 hi weights
    softmax_rows<<<B_ * T_, 256>>>(wts, wh);

    // 4) ctx = w @ vT^T  (2-term: wh*(vh+vl))
    gemm_f16pipe<2><<<dim3(D_ / 128, T_ / 128, B_), 256, SMEM_TOTAL>>>(
        wh, wh, vh, vl, ctx, S_, S_, D_, S_,
        (size_t)T_ * S_, (size_t)D_ * S_, (size_t)T_ * D_);
}

// round 14
// speedup vs baseline: 2.1053x; 1.1954x over previous
#include <cuda_runtime.h>
#include <cuda_fp16.h>
#include <cstdint>

// Luong dot attention via mma.sync.m16n8k16.f16.f32 (legacy HMMA path).
// R14: GEMM1 = 3-term fp16 split (hh+hl+lh), proven R12/R13 kernel.
//      GEMM2 = SINGLE-term fp16 (wh*vh), warp tile 64x64, 128-thread CTAs.
//   B=8, T=2048, S=2048, D=1024
// Output layout: [ctx (B*T*D) | weights (B*T*S)]; scores built in place.

#define B_ 8
#define T_ 2048
#define S_ 2048
#define D_ 1024

#define NQK ((size_t)B_ * T_ * D_)     // == B*S*D
#define NW  ((size_t)B_ * T_ * S_)

__device__ __align__(128) __half g_qh[NQK];
__device__ __align__(128) __half g_ql[NQK];
__device__ __align__(128) __half g_kh[NQK];
__device__ __align__(128) __half g_kl[NQK];
__device__ __align__(128) __half g_vh[NQK];   // V^T (B,D,S), fp16 hi only
__device__ __align__(128) __half g_wh[NW];

// ---------------------------------------------------------------- PTX helpers

__device__ __forceinline__ uint32_t smem_u32(const void* p) {
    uint32_t a;
    asm("{ .reg .u64 t; cvta.to.shared.u64 t, %1; cvt.u32.u64 %0, t; }"
        : "=r"(a) : "l"(p));
    return a;
}

__device__ __forceinline__ void cp16(uint32_t s, const void* g) {
    asm volatile("cp.async.cg.shared.global [%0], [%1], 16;"
                 :: "r"(s), "l"(__cvta_generic_to_global(g)) : "memory");
}
#define CP_COMMIT()  asm volatile("cp.async.commit_group;" ::: "memory")
#define CP_WAIT(n)   asm volatile("cp.async.wait_group %0;" :: "n"(n) : "memory")

#define LDSM4(r0, r1, r2, r3, addr)                                            \
    asm volatile("ldmatrix.sync.aligned.m8n8.x4.shared.b16 {%0,%1,%2,%3}, [%4];" \
                 : "=r"(r0), "=r"(r1), "=r"(r2), "=r"(r3) : "r"(addr))

#define MMA_F16(c, a, b)                                                       \
    asm volatile("mma.sync.aligned.m16n8k16.row.col.f32.f16.f16.f32 "          \
                 "{%0,%1,%2,%3}, {%4,%5,%6,%7}, {%8,%9}, {%0,%1,%2,%3};"       \
                 : "+f"((c)[0]), "+f"((c)[1]), "+f"((c)[2]), "+f"((c)[3])      \
                 : "r"((a)[0]), "r"((a)[1]), "r"((a)[2]), "r"((a)[3]),         \
                   "r"((b)[0]), "r"((b)[1]))

// Split a float4 into fp16 hi (rn) and fp16 lo (residual), packed as 2x half2.
__device__ __forceinline__ void split4(float4 v, uint2& hi, uint2& lo) {
    __half2 h0 = __floats2half2_rn(v.x, v.y);
    __half2 h1 = __floats2half2_rn(v.z, v.w);
    float2 f0 = __half22float2(h0);
    float2 f1 = __half22float2(h1);
    __half2 l0 = __floats2half2_rn(v.x - f0.x, v.y - f0.y);
    __half2 l1 = __floats2half2_rn(v.z - f1.x, v.w - f1.y);
    hi.x = *reinterpret_cast<uint32_t*>(&h0);
    hi.y = *reinterpret_cast<uint32_t*>(&h1);
    lo.x = *reinterpret_cast<uint32_t*>(&l0);
    lo.y = *reinterpret_cast<uint32_t*>(&l1);
}

// Swizzled offset within a 128-row x 32-half (64B/row) tile.
__device__ __forceinline__ uint32_t swz(int row, int c) {
    return ((uint32_t)row << 6) | ((uint32_t)((c ^ ((row >> 1) & 3)) & 3) << 4);
}

// ------------------------------------------------- GEMM1: 3-term split kernel
// C[M,N] = (Ah+Al)[M,K] * (Bh+Bl)[N,K]^T, terms hh+hl+lh.
// CTA 128x128, K-chunk 32, 256 threads (8 warps, warp tile 64x32).
// 3 stages x { AHI 8K | ALO 8K | BHI 8K | BLO 8K } = 96 KB -> 2 CTAs/SM.

#define OFF_AHI 0
#define OFF_ALO 8192
#define OFF_BHI 16384
#define OFF_BLO 24576
#define STAGE_BYTES 32768
#define NSTAGE 3
#define SMEM_TOTAL (NSTAGE * STAGE_BYTES)

__global__ __launch_bounds__(256, 2) void gemm_f16x3(
    const __half* __restrict__ Ah, const __half* __restrict__ Al,
    const __half* __restrict__ Bh, const __half* __restrict__ Bl,
    float* __restrict__ Cg, int lda, int ldb, int ldc, int K,
    size_t strideA, size_t strideB, size_t strideC)
{
    extern __shared__ char smem[];
    const uint32_t sb = smem_u32(smem);
    const int tid  = threadIdx.x;
    const int wid  = tid >> 5;
    const int lane = tid & 31;
    const size_t z = blockIdx.z;

    const __half* pAh = Ah + z * strideA + (size_t)(blockIdx.y * 128) * lda;
    const __half* pAl = Al + z * strideA + (size_t)(blockIdx.y * 128) * lda;
    const __half* pBh = Bh + z * strideB + (size_t)(blockIdx.x * 128) * ldb;
    const __half* pBl = Bl + z * strideB + (size_t)(blockIdx.x * 128) * ldb;
    float*        C   = Cg + z * strideC + (size_t)(blockIdx.y * 128) * ldc
                      + blockIdx.x * 128;

    const int warp_m = (wid & 1) * 64;
    const int warp_n = (wid >> 1) * 32;

    const int tile = lane >> 3;
    const int l8   = lane & 7;
    const int a_row0 = warp_m + ((tile & 1) << 3) + l8;
    const int a_usel = tile >> 1;
    const int b_row0 = warp_n + ((tile >> 1) << 3) + l8;
    const int b_usel = tile & 1;

#define CP_STAGE1(SBASE, K0)                                                   \
    {                                                                          \
        _Pragma("unroll")                                                      \
        for (int j = 0; j < 2; j++) {                                          \
            int idx = tid + 256 * j;                                           \
            int row = idx >> 2, c = idx & 3;                                   \
            uint32_t off = swz(row, c);                                        \
            size_t ga = (size_t)row * lda + (K0) + c * 8;                      \
            size_t gb = (size_t)row * ldb + (K0) + c * 8;                      \
            cp16((SBASE) + OFF_AHI + off, pAh + ga);                           \
            cp16((SBASE) + OFF_ALO + off, pAl + ga);                           \
            cp16((SBASE) + OFF_BHI + off, pBh + gb);                           \
            cp16((SBASE) + OFF_BLO + off, pBl + gb);                           \
        }                                                                      \
        CP_COMMIT();                                                           \
    }

    const int nc = K / 32;

    CP_STAGE1(sb, 0)
    CP_STAGE1(sb + STAGE_BYTES, 32)

    float acc[4][4][4];
#pragma unroll
    for (int i = 0; i < 4; i++)
#pragma unroll
        for (int j = 0; j < 4; j++) {
            acc[i][j][0] = 0.f; acc[i][j][1] = 0.f;
            acc[i][j][2] = 0.f; acc[i][j][3] = 0.f;
        }

    int cs = 0;

    for (int i = 0; i < nc; i++) {
        if (i == nc - 1) { CP_WAIT(0); } else { CP_WAIT(1); }
        __syncthreads();

        if (i + 2 < nc) {
            int is = cs + 2; if (is >= NSTAGE) is -= NSTAGE;
            CP_STAGE1(sb + (uint32_t)is * STAGE_BYTES, (i + 2) * 32)
        }

        const uint32_t st = sb + (uint32_t)cs * STAGE_BYTES;

#pragma unroll
        for (int ks = 0; ks < 2; ks++) {
            uint32_t ah[4][4], al[4][4], bh[4][2], bl[4][2];
#pragma unroll
            for (int mi = 0; mi < 4; mi++) {
                int row = a_row0 + mi * 16;
                uint32_t off = swz(row, ks * 2 + a_usel);
                LDSM4(ah[mi][0], ah[mi][1], ah[mi][2], ah[mi][3], st + OFF_AHI + off);
                LDSM4(al[mi][0], al[mi][1], al[mi][2], al[mi][3], st + OFF_ALO + off);
            }
#pragma unroll
            for (int nj = 0; nj < 2; nj++) {
                int row = b_row0 + nj * 16;
                uint32_t off = swz(row, ks * 2 + b_usel);
                LDSM4(bh[nj * 2][0], bh[nj * 2][1], bh[nj * 2 + 1][0], bh[nj * 2 + 1][1],
                      st + OFF_BHI + off);
                LDSM4(bl[nj * 2][0], bl[nj * 2][1], bl[nj * 2 + 1][0], bl[nj * 2 + 1][1],
                      st + OFF_BLO + off);
            }
#pragma unroll
            for (int mi = 0; mi < 4; mi++)
#pragma unroll
                for (int ni = 0; ni < 4; ni++)
                    MMA_F16(acc[mi][ni], ah[mi], bh[ni]);
#pragma unroll
            for (int mi = 0; mi < 4; mi++)
#pragma unroll
                for (int ni = 0; ni < 4; ni++)
                    MMA_F16(acc[mi][ni], ah[mi], bl[ni]);
#pragma unroll
            for (int mi = 0; mi < 4; mi++)
#pragma unroll
                for (int ni = 0; ni < 4; ni++)
                    MMA_F16(acc[mi][ni], al[mi], bh[ni]);
        }

        cs = cs + 1; if (cs >= NSTAGE) cs -= NSTAGE;
    }

    const int erow = warp_m + (lane >> 2);
    const int ecol = warp_n + 2 * (lane & 3);
#pragma unroll
    for (int mi = 0; mi < 4; mi++) {
#pragma unroll
        for (int ni = 0; ni < 4; ni++) {
            float* cp = C + (size_t)(erow + mi * 16) * ldc + ecol + ni * 8;
            *(float2*)cp = make_float2(acc[mi][ni][0], acc[mi][ni][1]);
            *(float2*)(cp + (size_t)8 * ldc) = make_float2(acc[mi][ni][2], acc[mi][ni][3]);
        }
    }
}

// ------------------------------------------------- GEMM2: single-term fp16
// C[M,N] = Ah[M,K] * Bh[N,K]^T.  CTA 128x128, 128 threads (4 warps),
// warp tile 64x64 (8 LDSM4 : 32 MMA), K-chunk 32,
// 3 stages x { A 8K | B 8K } = 48 KB -> 2 CTAs/SM.

#define OFF2_A 0
#define OFF2_B 8192
#define STAGE2_BYTES 16384
#define SMEM2_TOTAL (NSTAGE * STAGE2_BYTES)

__global__ __launch_bounds__(128, 2) void gemm_f16x1(
    const __half* __restrict__ Ah, const __half* __restrict__ Bh,
    float* __restrict__ Cg, int lda, int ldb, int ldc, int K,
    size_t strideA, size_t strideB, size_t strideC)
{
    extern __shared__ char smem[];
    const uint32_t sb = smem_u32(smem);
    const int tid  = threadIdx.x;
    const int wid  = tid >> 5;
    const int lane = tid & 31;
    const size_t z = blockIdx.z;

    const __half* pAh = Ah + z * strideA + (size_t)(blockIdx.y * 128) * lda;
    const __half* pBh = Bh + z * strideB + (size_t)(blockIdx.x * 128) * ldb;
    float*        C   = Cg + z * strideC + (size_t)(blockIdx.y * 128) * ldc
                      + blockIdx.x * 128;

    const int warp_m = (wid & 1) * 64;
    const int warp_n = (wid >> 1) * 64;

    const int tile = lane >> 3;
    const int l8   = lane & 7;
    const int a_row0 = warp_m + ((tile & 1) << 3) + l8;
    const int a_usel = tile >> 1;
    const int b_row0 = warp_n + ((tile >> 1) << 3) + l8;
    const int b_usel = tile & 1;

#define CP_STAGE2(SBASE, K0)                                                   \
    {                                                                          \
        _Pragma("unroll")                                                      \
        for (int j = 0; j < 4; j++) {                                          \
            int idx = tid + 128 * j;                                           \
            int row = idx >> 2, c = idx & 3;                                   \
            uint32_t off = swz(row, c);                                        \
            cp16((SBASE) + OFF2_A + off, pAh + (size_t)row * lda + (K0) + c * 8); \
            cp16((SBASE) + OFF2_B + off, pBh + (size_t)row * ldb + (K0) + c * 8); \
        }                                                                      \
        CP_COMMIT();                                                           \
    }

    const int nc = K / 32;

    CP_STAGE2(sb, 0)
    CP_STAGE2(sb + STAGE2_BYTES, 32)

    float acc[4][8][4];
#pragma unroll
    for (int i = 0; i < 4; i++)
#pragma unroll
        for (int j = 0; j < 8; j++) {
            acc[i][j][0] = 0.f; acc[i][j][1] = 0.f;
            acc[i][j][2] = 0.f; acc[i][j][3] = 0.f;
        }

    int cs = 0;

    for (int i = 0; i < nc; i++) {
        if (i == nc - 1) { CP_WAIT(0); } else { CP_WAIT(1); }
        __syncthreads();

        if (i + 2 < nc) {
            int is = cs + 2; if (is >= NSTAGE) is -= NSTAGE;
            CP_STAGE2(sb + (uint32_t)is * STAGE2_BYTES, (i + 2) * 32)
        }

        const uint32_t st = sb + (uint32_t)cs * STAGE2_BYTES;

#pragma unroll
        for (int ks = 0; ks < 2; ks++) {
            uint32_t ah[4][4], bh[8][2];
#pragma unroll
            for (int mi = 0; mi < 4; mi++) {
                int row = a_row0 + mi * 16;
                uint32_t off = swz(row, ks * 2 + a_usel);
                LDSM4(ah[mi][0], ah[mi][1], ah[mi][2], ah[mi][3], st + OFF2_A + off);
            }
#pragma unroll
            for (int nj = 0; nj < 4; nj++) {
                int row = b_row0 + nj * 16;
                uint32_t off = swz(row, ks * 2 + b_usel);
                LDSM4(bh[nj * 2][0], bh[nj * 2][1], bh[nj * 2 + 1][0], bh[nj * 2 + 1][1],
                      st + OFF2_B + off);
            }
#pragma unroll
            for (int mi = 0; mi < 4; mi++)
#pragma unroll
                for (int ni = 0; ni < 8; ni++)
                    MMA_F16(acc[mi][ni], ah[mi], bh[ni]);
        }

        cs = cs + 1; if (cs >= NSTAGE) cs -= NSTAGE;
    }

    const int erow = warp_m + (lane >> 2);
    const int ecol = warp_n + 2 * (lane & 3);
#pragma unroll
    for (int mi = 0; mi < 4; mi++) {
#pragma unroll
        for (int ni = 0; ni < 8; ni++) {
            float* cp = C + (size_t)(erow + mi * 16) * ldc + ecol + ni * 8;
            *(float2*)cp = make_float2(acc[mi][ni][0], acc[mi][ni][1]);
            *(float2*)(cp + (size_t)8 * ldc) = make_float2(acc[mi][ni][2], acc[mi][ni][3]);
        }
    }
}

// ------------------------------------------------- split fp32 -> fp16 hi/lo

__global__ void split_f32(const float* __restrict__ in,
                          __half* __restrict__ hi, __half* __restrict__ lo,
                          int n4)
{
    int idx = blockIdx.x * blockDim.x + threadIdx.x;
    if (idx < n4) {
        float4 v = ((const float4*)in)[idx];
        uint2 h, l;
        split4(v, h, l);
        ((uint2*)hi)[idx] = h;
        ((uint2*)lo)[idx] = l;
    }
}

// ------------------------------------- transpose + fp16(hi): vT from src

__global__ void transpose_half(const float* __restrict__ src,
                               __half* __restrict__ vh)
{
    __shared__ float t[32][33];
    const int b = blockIdx.z;
    const int s0 = blockIdx.x * 32;
    const int d0 = blockIdx.y * 32;
    const float* sp = src + (size_t)b * S_ * D_;
    __half* hp = vh + (size_t)b * D_ * S_;
    const int tx = threadIdx.x, ty = threadIdx.y;
#pragma unroll
    for (int i = 0; i < 32; i += 8)
        t[ty + i][tx] = sp[(size_t)(s0 + ty + i) * D_ + d0 + tx];
    __syncthreads();
#pragma unroll
    for (int i = 0; i < 32; i += 8)
        hp[(size_t)(d0 + ty + i) * S_ + s0 + tx] = __float2half_rn(t[tx][ty + i]);
}

// ---------------------------------------------------------------- softmax
// In-place softmax over S; also emits fp16 hi of the weights.

__global__ void softmax_rows(float* __restrict__ w, __half* __restrict__ wh)
{
    __shared__ float redm[8];
    __shared__ float reds[8];
    const int tid  = threadIdx.x;
    const int lane = tid & 31;
    const int wid  = tid >> 5;
    const size_t roff = (size_t)blockIdx.x * S_;
    float* p = w + roff;

    float4 v0 = *(const float4*)(p + tid * 4);
    float4 v1 = *(const float4*)(p + 1024 + tid * 4);

    float mx = fmaxf(fmaxf(fmaxf(v0.x, v0.y), fmaxf(v0.z, v0.w)),
                     fmaxf(fmaxf(v1.x, v1.y), fmaxf(v1.z, v1.w)));
#pragma unroll
    for (int o = 16; o; o >>= 1)
        mx = fmaxf(mx, __shfl_xor_sync(0xffffffffu, mx, o));
    if (lane == 0) redm[wid] = mx;
    __syncthreads();
    if (tid < 32) {
        float m = (tid < 8) ? redm[tid] : -3.402823466e38f;
#pragma unroll
        for (int o = 4; o; o >>= 1)
            m = fmaxf(m, __shfl_xor_sync(0xffffffffu, m, o));
        if (tid == 0) redm[0] = m;
    }
    __syncthreads();
    const float bm = redm[0];

    v0.x = __expf(v0.x - bm); v0.y = __expf(v0.y - bm);
    v0.z = __expf(v0.z - bm); v0.w = __expf(v0.w - bm);
    v1.x = __expf(v1.x - bm); v1.y = __expf(v1.y - bm);
    v1.z = __expf(v1.z - bm); v1.w = __expf(v1.w - bm);

    float sm = v0.x + v0.y + v0.z + v0.w + v1.x + v1.y + v1.z + v1.w;
#pragma unroll
    for (int o = 16; o; o >>= 1)
        sm += __shfl_xor_sync(0xffffffffu, sm, o);
    if (lane == 0) reds[wid] = sm;
    __syncthreads();
    if (tid < 32) {
        float t = (tid < 8) ? reds[tid] : 0.0f;
#pragma unroll
        for (int o = 4; o; o >>= 1)
            t += __shfl_xor_sync(0xffffffffu, t, o);
        if (tid == 0) reds[0] = t;
    }
    __syncthreads();
    const float inv = 1.0f / reds[0];

    v0.x *= inv; v0.y *= inv; v0.z *= inv; v0.w *= inv;
    v1.x *= inv; v1.y *= inv; v1.z *= inv; v1.w *= inv;
    *(float4*)(p + tid * 4)        = v0;
    *(float4*)(p + 1024 + tid * 4) = v1;

    __half2 h0 = __floats2half2_rn(v0.x, v0.y);
    __half2 h1 = __floats2half2_rn(v0.z, v0.w);
    __half2 h2 = __floats2half2_rn(v1.x, v1.y);
    __half2 h3 = __floats2half2_rn(v1.z, v1.w);
    uint2 u0, u1;
    u0.x = *reinterpret_cast<uint32_t*>(&h0);
    u0.y = *reinterpret_cast<uint32_t*>(&h1);
    u1.x = *reinterpret_cast<uint32_t*>(&h2);
    u1.y = *reinterpret_cast<uint32_t*>(&h3);
    *(uint2*)(wh + roff + tid * 4)        = u0;
    *(uint2*)(wh + roff + 1024 + tid * 4) = u1;
}

// ---------------------------------------------------------------- launch

extern "C" void kernel_launch(void* const* d_in, const int* in_sizes, int n_in,
                              void* d_out, int out_size)
{
    const float* trg = (const float*)d_in[0];   // (B, T, D)
    const float* src = (const float*)d_in[1];   // (B, S, D)
    float* ctx = (float*)d_out;                           // (B, T, D)
    float* wts = (float*)d_out + (size_t)B_ * T_ * D_;    // (B, T, S)

    __half *qh, *ql, *kh, *kl, *vh, *wh;
    void* p;
    cudaGetSymbolAddress(&p, g_qh); qh = (__half*)p;
    cudaGetSymbolAddress(&p, g_ql); ql = (__half*)p;
    cudaGetSymbolAddress(&p, g_kh); kh = (__half*)p;
    cudaGetSymbolAddress(&p, g_kl); kl = (__half*)p;
    cudaGetSymbolAddress(&p, g_vh); vh = (__half*)p;
    cudaGetSymbolAddress(&p, g_wh); wh = (__half*)p;

    cudaFuncSetAttribute(gemm_f16x3,
                         cudaFuncAttributeMaxDynamicSharedMemorySize, SMEM_TOTAL);
    cudaFuncSetAttribute(gemm_f16x1,
                         cudaFuncAttributeMaxDynamicSharedMemorySize, SMEM2_TOTAL);

    const int n4 = (int)(NQK / 4);

    // 1) split q, k ; transpose v -> fp16 hi
    split_f32<<<(n4 + 255) / 256, 256>>>(trg, qh, ql, n4);
    split_f32<<<(n4 + 255) / 256, 256>>>(src, kh, kl, n4);
    transpose_half<<<dim3(S_ / 32, D_ / 32, B_), dim3(32, 8)>>>(src, vh);

    // 2) scores = q @ k^T  (3-term)
    gemm_f16x3<<<dim3(S_ / 128, T_ / 128, B_), 256, SMEM_TOTAL>>>(
        qh, ql, kh, kl, wts, D_, D_, S_, D_,
        (size_t)T_ * D_, (size_t)S_ * D_, (size_t)T_ * S_);

    // 3) softmax rows in place + emit fp16 hi weights
    softmax_rows<<<B_ * T_, 256>>>(wts, wh);

    // 4) ctx = wh @ vh^T  (single term)
    gemm_f16x1<<<dim3(D_ / 128, T_ / 128, B_), 128, SMEM2_TOTAL>>>(
        wh, vh, ctx, S_, S_, D_, S_,
        (size_t)T_ * S_, (size_t)D_ * S_, (size_t)T_ * D_);
}